// round 15
// baseline (speedup 1.0000x reference)
#include <cuda_runtime.h>
#include <cuda_fp16.h>
#include <mma.h>
#include <cstdint>

using namespace nvcuda;

// Problem constants
#define MM     8192      // BATCH*SEQ
#define DMODEL 1024
#define DINNER 2048
#define DSTATE 16
#define NBATCH 4
#define SEQLEN 2048
#define NCHUNK 8
#define CLEN   256       // SEQLEN / NCHUNK
#define NBLK   (CLEN / 32)

// ---------------- scratch (device globals: allocation-free) ----------------
__device__ __half g_uh [MM * DINNER];      // silu(x_proj) half
__device__ __half g_szh[MM * DINNER];      // silu(z) half
__device__ float  g_dt [MM * DINNER];      // softplus(dt) fp32 (exponent input)
__device__ float  g_xd [MM * 32];          // [B|C] projection
__device__ __half g_ymh[MM * DINNER];      // y * silu(z) half (out GEMM)
__device__ __half g_xh [MM * DMODEL];      // half x
__device__ __half g_w1 [DMODEL * 4096];    // half W_in
__device__ __half g_w2 [DINNER * DINNER];  // half W_dt
__device__ __half g_w3 [DINNER * DMODEL];  // half W_out
__device__ float  g_wxt[32 * DINNER];      // W_xproj^T fp32 [32][2048]
__device__ float  g_hend  [NBATCH * NCHUNK * DINNER * DSTATE];
__device__ float  g_hstart[NBATCH * NCHUNK * DINNER * DSTATE];
__device__ float  g_sdt   [NBATCH * NCHUNK * DINNER];

__device__ __forceinline__ float siluf(float v) { return v / (1.f + __expf(-v)); }
__device__ __forceinline__ float softplusf(float v) {
    return fmaxf(v, 0.f) + log1pf(__expf(-fabsf(v)));
}
__device__ __forceinline__ float ex2(float x) {
    float r; asm("ex2.approx.f32 %0, %1;" : "=f"(r) : "f"(x)); return r;
}

// ---------------- cp.async helpers ----------------------------------------
__device__ __forceinline__ void cp16(void* s, const void* g) {
    unsigned sa = (unsigned)__cvta_generic_to_shared(s);
    asm volatile("cp.async.cg.shared.global [%0], [%1], 16;\n" :: "r"(sa), "l"(g));
}
__device__ __forceinline__ void cp_commit() {
    asm volatile("cp.async.commit_group;\n" ::: "memory");
}
template<int N> __device__ __forceinline__ void cp_wait() {
    asm volatile("cp.async.wait_group %0;\n" :: "n"(N) : "memory");
}

// ---------------- fp16 WMMA GEMM (BK=64: 32 HMMA per barrier pair) ----------
// C = A[MxK] @ B[KxN] + bias (A,B half; accum fp32). 8 warps, warp tile
// 64x32, block tile 128x128x64, 2-stage cp.async. Epilogue reuses A region.
// EPI 0: silu; cols<2048 -> outh0 (half), else -> outh1 (half)
// EPI 1: softplus -> out0 f32
// EPI 2: plain    -> out0 f32
constexpr int AS_STRIDE = 72;                 // 64 + 8 pad (halves)
constexpr int BS_STRIDE = 136;                // 128 + 8 pad
constexpr int AS_TILE   = 128 * AS_STRIDE;    // 9216 halves
constexpr int BS_TILE   = 64 * BS_STRIDE;     // 8704 halves
constexpr int GEMM_SMEM_BYTES = 2 * (AS_TILE + BS_TILE) * 2;   // 71680 B

template<int EPI>
__global__ __launch_bounds__(256) void gemm_fp16(
    const __half* __restrict__ A, const __half* __restrict__ B,
    const float* __restrict__ bias,
    float* __restrict__ out0, __half* __restrict__ outh0,
    __half* __restrict__ outh1,
    int M, int N, int K)
{
    extern __shared__ char smem[];
    __half* As = (__half*)smem;                       // [2][128][72]
    __half* Bs = (__half*)smem + 2 * AS_TILE;         // [2][64][136]
    float*  Epi = (float*)smem;                       // reused post-loop (8KB)

    const int tid  = threadIdx.x;
    const int wid  = tid >> 5;   // 0..7
    const int lane = tid & 31;
    const int wm   = wid >> 2;   // 0..1 -> 64-row half
    const int wn   = wid & 3;    // 0..3 -> 32-col quarter
    const int m0   = blockIdx.y * 128;
    const int n0   = blockIdx.x * 128;

    // A: 128 rows x 64 halves = 1024 chunks of 8 halves (4/thread)
    const int arow = tid >> 2;            // + r*64 (2 iters, 2 chunks each? no:)
    const int ac16 = tid & 3;             // 4 chunks per row
    // B: 64 rows x 128 halves = 1024 chunks (4/thread)
    const int brow = tid >> 4;            // + r*16 (4 iters)
    const int bc16 = tid & 15;

    wmma::fragment<wmma::accumulator, 16, 16, 16, float> acc[4][2];
    #pragma unroll
    for (int i = 0; i < 4; i++)
        #pragma unroll
        for (int j = 0; j < 2; j++)
            wmma::fill_fragment(acc[i][j], 0.f);

    const int NIT = K >> 6;

    auto load_ab = [&](int buf, int k0) {
        __half* da = As + buf * AS_TILE;
        __half* db = Bs + buf * BS_TILE;
        // A tile: rows 0..127, each row 64 halves = 4 chunks; tid covers
        // (row=tid>>2, chunk=tid&3) + r*64 rows -> 2 iters * 256 thr * 1 chunk
        // = 512 chunks/iter-pair... need 1024 chunks total => 2 chunks/thread
        // via r in {0,1} over rows AND full chunk index:
        #pragma unroll
        for (int r = 0; r < 2; r++) {
            int row = arow + r * 64;
            cp16(&da[row * AS_STRIDE + ac16 * 16],
                 &A[(size_t)(m0 + row) * K + k0 + ac16 * 16]);
            cp16(&da[row * AS_STRIDE + ac16 * 16 + 8],
                 &A[(size_t)(m0 + row) * K + k0 + ac16 * 16 + 8]);
        }
        // B tile: 64 rows x 128 halves = 1024 chunks; (row=tid>>4 + r*16,
        // chunk=tid&15), r in 0..3 -> 4 chunks/thread
        #pragma unroll
        for (int r = 0; r < 4; r++) {
            int row = brow + r * 16;
            cp16(&db[row * BS_STRIDE + bc16 * 8],
                 &B[(size_t)(k0 + row) * N + n0 + bc16 * 8]);
        }
        cp_commit();
    };

    load_ab(0, 0);

    for (int it = 0; it < NIT; it++) {
        const int buf = it & 1;
        if (it + 1 < NIT) {
            load_ab(buf ^ 1, (it + 1) << 6);
            cp_wait<1>();
        } else {
            cp_wait<0>();
        }
        __syncthreads();

        const __half* ca = As + buf * AS_TILE;
        const __half* cb = Bs + buf * BS_TILE;
        #pragma unroll
        for (int kk = 0; kk < 64; kk += 16) {
            wmma::fragment<wmma::matrix_a, 16, 16, 16, __half, wmma::row_major> af[4];
            wmma::fragment<wmma::matrix_b, 16, 16, 16, __half, wmma::row_major> bf[2];
            #pragma unroll
            for (int i = 0; i < 4; i++)
                wmma::load_matrix_sync(af[i],
                    &ca[(wm * 64 + i * 16) * AS_STRIDE + kk], AS_STRIDE);
            #pragma unroll
            for (int j = 0; j < 2; j++)
                wmma::load_matrix_sync(bf[j],
                    &cb[kk * BS_STRIDE + wn * 32 + j * 16], BS_STRIDE);
            #pragma unroll
            for (int i = 0; i < 4; i++)
                #pragma unroll
                for (int j = 0; j < 2; j++)
                    wmma::mma_sync(acc[i][j], af[i], bf[j], acc[i][j]);
        }
        __syncthreads();
    }
    // last loop iteration ended with __syncthreads(): safe to reuse As as Epi

    float* EpiW = Epi + wid * 256;
    #pragma unroll
    for (int i = 0; i < 4; i++) {
        #pragma unroll
        for (int j = 0; j < 2; j++) {
            wmma::store_matrix_sync(EpiW, acc[i][j], 16, wmma::mem_row_major);
            __syncwarp();
            int gr0 = m0 + wm * 64 + i * 16;
            int gc0 = n0 + wn * 32 + j * 16;
            #pragma unroll
            for (int e = 0; e < 8; e++) {
                int idx = lane + e * 32;
                int r = idx >> 4, c = idx & 15;
                int gr = gr0 + r, gc = gc0 + c;
                float v = EpiW[r * 16 + c] + bias[gc];
                if (EPI == 0) {
                    float sv = siluf(v);
                    if (gc < DINNER)
                        outh0[(size_t)gr * DINNER + gc] = __float2half(sv);
                    else
                        outh1[(size_t)gr * DINNER + gc - DINNER] = __float2half(sv);
                } else if (EPI == 1) {
                    out0[(size_t)gr * DINNER + gc] = softplusf(v);
                } else {
                    out0[(size_t)gr * (size_t)N + gc] = v;
                }
            }
            __syncwarp();
        }
    }
}

// ---------------- fused prep: all fp32->fp16 copies + W_xproj transpose -----
#define P_S0 1048576                // x:     8M elems / 8
#define P_S1 (P_S0 + 524288)        // W_in:  4M / 8
#define P_S2 (P_S1 + 524288)        // W_dt:  4M / 8
#define P_S3 (P_S2 + 262144)        // W_out: 2M / 8
#define P_S4 (P_S3 + 16384)         // WT:    64K / 4
#define P_BLOCKS (P_S4 / 256)       // 9280

__device__ __forceinline__ void half8(const float* __restrict__ src,
                                      __half* __restrict__ dst, long u)
{
    long i = u * 8;
    float4 a = *(const float4*)&src[i];
    float4 b = *(const float4*)&src[i + 4];
    __half2 h[4];
    h[0] = __floats2half2_rn(a.x, a.y);
    h[1] = __floats2half2_rn(a.z, a.w);
    h[2] = __floats2half2_rn(b.x, b.y);
    h[3] = __floats2half2_rn(b.z, b.w);
    *(uint4*)&dst[i] = *(uint4*)h;
}

__global__ __launch_bounds__(256) void prep_all(
    const float* __restrict__ x,    const float* __restrict__ W_in,
    const float* __restrict__ W_dt, const float* __restrict__ W_out,
    const float* __restrict__ W_xp,
    __half* __restrict__ xh, __half* __restrict__ w1,
    __half* __restrict__ w2, __half* __restrict__ w3,
    float* __restrict__ wxt)
{
    long u = (long)blockIdx.x * 256 + threadIdx.x;
    if (u < P_S0)      half8(x,     xh, u);
    else if (u < P_S1) half8(W_in,  w1, u - P_S0);
    else if (u < P_S2) half8(W_dt,  w2, u - P_S1);
    else if (u < P_S3) half8(W_out, w3, u - P_S2);
    else {
        long j = u - P_S3;            // 16384 units: WT[c][k0..k0+3]
        int c  = (int)(j & 31);
        int k0 = (int)(j >> 5) * 4;
        float4 v;
        v.x = W_xp[(size_t)(k0 + 0) * 32 + c];
        v.y = W_xp[(size_t)(k0 + 1) * 32 + c];
        v.z = W_xp[(size_t)(k0 + 2) * 32 + c];
        v.w = W_xp[(size_t)(k0 + 3) * 32 + c];
        *(float4*)&wxt[(size_t)c * DINNER + k0] = v;
    }
}

// ---------------- skinny projection: xdbl = u @ W_xproj + b ----------------
__global__ __launch_bounds__(256) void xproj_kernel(
    const __half* __restrict__ uh, const float* __restrict__ WT,
    const float* __restrict__ bias, float* __restrict__ xdbl)
{
    __shared__ __align__(16) float WTs[32][68];
    __shared__ __align__(16) float Us[8][64];

    const int tid  = threadIdx.x;
    const int wid  = tid >> 5;     // row within block (0..7)
    const int lane = tid & 31;     // output column
    const size_t row = (size_t)blockIdx.x * 8 + wid;

    float acc = 0.f;
    for (int k0 = 0; k0 < DINNER; k0 += 64) {
        {
            int c = tid >> 3, kk = (tid & 7) * 8;
            float4 a = *(const float4*)&WT[(size_t)c * DINNER + k0 + kk];
            float4 b = *(const float4*)&WT[(size_t)c * DINNER + k0 + kk + 4];
            *(float4*)&WTs[c][kk]     = a;
            *(float4*)&WTs[c][kk + 4] = b;
        }
        if (tid < 64) {
            int r = tid >> 3, kk = (tid & 7) * 8;
            const __half* up =
                &uh[((size_t)blockIdx.x * 8 + r) * DINNER + k0 + kk];
            float4 f0, f1;
            f0.x = __half2float(up[0]); f0.y = __half2float(up[1]);
            f0.z = __half2float(up[2]); f0.w = __half2float(up[3]);
            f1.x = __half2float(up[4]); f1.y = __half2float(up[5]);
            f1.z = __half2float(up[6]); f1.w = __half2float(up[7]);
            *(float4*)&Us[r][kk]     = f0;
            *(float4*)&Us[r][kk + 4] = f1;
        }
        __syncthreads();

        #pragma unroll
        for (int kk = 0; kk < 64; kk += 4) {
            float4 w  = *(const float4*)&WTs[lane][kk];
            float4 uu = *(const float4*)&Us[wid][kk];
            acc = fmaf(uu.x, w.x, acc);
            acc = fmaf(uu.y, w.y, acc);
            acc = fmaf(uu.z, w.z, acc);
            acc = fmaf(uu.w, w.w, acc);
        }
        __syncthreads();
    }
    xdbl[row * 32 + lane] = acc + bias[lane];
}

// ---------------- chunked selective scan (software-pipelined staging) -------
// Pass 1: local recurrence h0=0 -> h_end, sum(dt).
__global__ __launch_bounds__(256) void scan_pass1(
    const __half* __restrict__ uh, const float* __restrict__ dt,
    const float* __restrict__ xdbl, const float* __restrict__ A_log,
    float* __restrict__ hend, float* __restrict__ sdtg)
{
    __shared__ __half Uh[2][32][64];
    __shared__ float  Dt[2][32][64];
    __shared__ float  XD[2][32][32];

    const int b    = blockIdx.z;
    const int c    = blockIdx.y;
    const int d0   = blockIdx.x * 64;
    const int tid  = threadIdx.x;
    const int wid  = tid >> 5;
    const int lane = tid & 31;
    const int dq   = lane >> 2;
    const int sq   = lane & 3;
    const int dl   = wid * 8 + dq;
    const int d    = d0 + dl;

    float Ap[4], h[4] = {0.f, 0.f, 0.f, 0.f};
    #pragma unroll
    for (int i = 0; i < 4; i++)
        Ap[i] = -__expf(A_log[d * DSTATE + sq * 4 + i]) * 1.4426950408889634f;
    float sdt = 0.f;
    const size_t base = (size_t)b * SEQLEN * DINNER;
    const int tstart = c * CLEN;

    const int ut_t = tid >> 3, ut_g = tid & 7;
    const int xd_t = tid >> 3, xd_g = tid & 7;

    uint4  uReg;
    float4 dReg0, dReg1;
    float4 xReg;

    auto ldg_block = [&](int t0) {
        uReg = *(const uint4*)&uh[base + (size_t)(t0 + ut_t) * DINNER + d0 + ut_g * 8];
        {
            int tt = tid >> 4, gg = tid & 15;
            dReg0 = *(const float4*)&dt[base + (size_t)(t0 + tt) * DINNER + d0 + gg * 4];
            int idx = tid + 256; tt = idx >> 4; gg = idx & 15;
            dReg1 = *(const float4*)&dt[base + (size_t)(t0 + tt) * DINNER + d0 + gg * 4];
        }
        xReg = *(const float4*)&xdbl[((size_t)b * SEQLEN + t0 + xd_t) * 32 + xd_g * 4];
    };
    auto sts_block = [&](int bf) {
        *(uint4*)&Uh[bf][ut_t][ut_g * 8] = uReg;
        {
            int tt = tid >> 4, gg = tid & 15;
            *(float4*)&Dt[bf][tt][gg * 4] = dReg0;
            int idx = tid + 256; tt = idx >> 4; gg = idx & 15;
            *(float4*)&Dt[bf][tt][gg * 4] = dReg1;
        }
        *(float4*)&XD[bf][xd_t][xd_g * 4] = xReg;
    };

    ldg_block(tstart);
    sts_block(0);
    __syncthreads();

    for (int blk = 0; blk < NBLK; blk++) {
        const int bf = blk & 1;
        const bool more = (blk + 1 < NBLK);
        if (more) ldg_block(tstart + (blk + 1) * 32);

        #pragma unroll 4
        for (int t = 0; t < 32; t++) {
            float uv  = __half2float(Uh[bf][t][dl]);
            float dtv = Dt[bf][t][dl];
            float4 Bv = *(const float4*)&XD[bf][t][sq * 4];
            float du  = dtv * uv;
            sdt += dtv;
            h[0] = fmaf(h[0], ex2(dtv * Ap[0]), du * Bv.x);
            h[1] = fmaf(h[1], ex2(dtv * Ap[1]), du * Bv.y);
            h[2] = fmaf(h[2], ex2(dtv * Ap[2]), du * Bv.z);
            h[3] = fmaf(h[3], ex2(dtv * Ap[3]), du * Bv.w);
        }
        if (more) sts_block(bf ^ 1);
        __syncthreads();
    }

    size_t ho = ((size_t)(b * NCHUNK + c) * DINNER + d) * DSTATE + sq * 4;
    *(float4*)&hend[ho] = make_float4(h[0], h[1], h[2], h[3]);
    if (sq == 0) sdtg[(size_t)(b * NCHUNK + c) * DINNER + d] = sdt;
}

// Fix: sequential chain over chunks. thread = one (b,d,s).
__global__ __launch_bounds__(256) void scan_fix(
    const float* __restrict__ A_log, const float* __restrict__ hend,
    const float* __restrict__ sdtg, float* __restrict__ hstart)
{
    int idx = blockIdx.x * 256 + threadIdx.x;
    int s = idx & 15;
    int d = (idx >> 4) & (DINNER - 1);
    int b = idx >> 15;
    float Ap = -__expf(A_log[d * DSTATE + s]) * 1.4426950408889634f;
    float hs = 0.f;
    hstart[((size_t)(b * NCHUNK) * DINNER + d) * DSTATE + s] = 0.f;
    #pragma unroll
    for (int c = 1; c < NCHUNK; c++) {
        size_t pc = (size_t)(b * NCHUNK + c - 1) * DINNER + d;
        float P = ex2(Ap * sdtg[pc]);
        hs = fmaf(P, hs, hend[pc * DSTATE + s]);
        hstart[((size_t)(b * NCHUNK + c) * DINNER + d) * DSTATE + s] = hs;
    }
}

// Pass 2: full scan within chunk, seeded with h_start; fused * silu(z).
__global__ __launch_bounds__(256) void scan_pass2(
    const __half* __restrict__ uh, const float* __restrict__ dt,
    const float* __restrict__ xdbl, const __half* __restrict__ szh,
    const float* __restrict__ A_log, const float* __restrict__ Dp,
    const float* __restrict__ hstart, __half* __restrict__ ymh)
{
    __shared__ __half Uh[2][32][64];
    __shared__ float  Dt[2][32][64];
    __shared__ __half Sz[2][32][64];
    __shared__ float  XD[2][32][32];

    const int b    = blockIdx.z;
    const int c    = blockIdx.y;
    const int d0   = blockIdx.x * 64;
    const int tid  = threadIdx.x;
    const int wid  = tid >> 5;
    const int lane = tid & 31;
    const int dq   = lane >> 2;
    const int sq   = lane & 3;
    const int dl   = wid * 8 + dq;
    const int d    = d0 + dl;

    float Ap[4], h[4];
    #pragma unroll
    for (int i = 0; i < 4; i++)
        Ap[i] = -__expf(A_log[d * DSTATE + sq * 4 + i]) * 1.4426950408889634f;
    {
        float4 h0 = *(const float4*)
            &hstart[((size_t)(b * NCHUNK + c) * DINNER + d) * DSTATE + sq * 4];
        h[0] = h0.x; h[1] = h0.y; h[2] = h0.z; h[3] = h0.w;
    }
    const float Dv = Dp[d];
    const size_t base = (size_t)b * SEQLEN * DINNER;
    const int tstart = c * CLEN;

    const int ut_t = tid >> 3, ut_g = tid & 7;
    const int xd_t = tid >> 3, xd_g = tid & 7;

    uint4  uReg, zReg;
    float4 dReg0, dReg1;
    float4 xReg;

    auto ldg_block = [&](int t0) {
        size_t go = base + (size_t)(t0 + ut_t) * DINNER + d0 + ut_g * 8;
        uReg = *(const uint4*)&uh[go];
        zReg = *(const uint4*)&szh[go];
        {
            int tt = tid >> 4, gg = tid & 15;
            dReg0 = *(const float4*)&dt[base + (size_t)(t0 + tt) * DINNER + d0 + gg * 4];
            int idx = tid + 256; tt = idx >> 4; gg = idx & 15;
            dReg1 = *(const float4*)&dt[base + (size_t)(t0 + tt) * DINNER + d0 + gg * 4];
        }
        xReg = *(const float4*)&xdbl[((size_t)b * SEQLEN + t0 + xd_t) * 32 + xd_g * 4];
    };
    auto sts_block = [&](int bf) {
        *(uint4*)&Uh[bf][ut_t][ut_g * 8] = uReg;
        *(uint4*)&Sz[bf][ut_t][ut_g * 8] = zReg;
        {
            int tt = tid >> 4, gg = tid & 15;
            *(float4*)&Dt[bf][tt][gg * 4] = dReg0;
            int idx = tid + 256; tt = idx >> 4; gg = idx & 15;
            *(float4*)&Dt[bf][tt][gg * 4] = dReg1;
        }
        *(float4*)&XD[bf][xd_t][xd_g * 4] = xReg;
    };

    ldg_block(tstart);
    sts_block(0);
    __syncthreads();

    for (int blk = 0; blk < NBLK; blk++) {
        const int bf = blk & 1;
        const bool more = (blk + 1 < NBLK);
        const int t0 = tstart + blk * 32;
        if (more) ldg_block(t0 + 32);

        #pragma unroll 4
        for (int t = 0; t < 32; t++) {
            float uv  = __half2float(Uh[bf][t][dl]);
            float dtv = Dt[bf][t][dl];
            float4 Bv = *(const float4*)&XD[bf][t][sq * 4];
            float4 Cv = *(const float4*)&XD[bf][t][16 + sq * 4];
            float du  = dtv * uv;
            float p;
            h[0] = fmaf(h[0], ex2(dtv * Ap[0]), du * Bv.x);
            h[1] = fmaf(h[1], ex2(dtv * Ap[1]), du * Bv.y);
            h[2] = fmaf(h[2], ex2(dtv * Ap[2]), du * Bv.z);
            h[3] = fmaf(h[3], ex2(dtv * Ap[3]), du * Bv.w);
            p  = h[0] * Cv.x;
            p  = fmaf(h[1], Cv.y, p);
            p  = fmaf(h[2], Cv.z, p);
            p  = fmaf(h[3], Cv.w, p);
            p += __shfl_xor_sync(0xffffffffu, p, 1);
            p += __shfl_xor_sync(0xffffffffu, p, 2);
            if (sq == 0) {
                float zv = __half2float(Sz[bf][t][dl]);
                float y  = fmaf(Dv, uv, p);
                ymh[base + (size_t)(t0 + t) * DINNER + d] = __float2half(y * zv);
            }
        }
        if (more) sts_block(bf ^ 1);
        __syncthreads();
    }
}

// ---------------- launch ---------------------------------------------------
extern "C" void kernel_launch(void* const* d_in, const int* in_sizes, int n_in,
                              void* d_out, int out_size)
{
    const float* x     = (const float*)d_in[0];
    const float* W_in  = (const float*)d_in[1];
    const float* b_in  = (const float*)d_in[2];
    const float* W_xp  = (const float*)d_in[3];
    const float* b_xp  = (const float*)d_in[4];
    const float* W_dt  = (const float*)d_in[5];
    const float* b_dt  = (const float*)d_in[6];
    const float* W_out = (const float*)d_in[7];
    const float* b_out = (const float*)d_in[8];
    const float* A_log = (const float*)d_in[9];
    const float* D_par = (const float*)d_in[10];
    float* out = (float*)d_out;

    float *dtb, *xd, *wxt, *hend, *hstart, *sdt;
    __half *uh, *szh, *ymh, *xh, *w1, *w2, *w3;
    cudaGetSymbolAddress((void**)&uh,  g_uh);
    cudaGetSymbolAddress((void**)&szh, g_szh);
    cudaGetSymbolAddress((void**)&dtb, g_dt);
    cudaGetSymbolAddress((void**)&xd,  g_xd);
    cudaGetSymbolAddress((void**)&ymh, g_ymh);
    cudaGetSymbolAddress((void**)&xh,  g_xh);
    cudaGetSymbolAddress((void**)&w1,  g_w1);
    cudaGetSymbolAddress((void**)&w2,  g_w2);
    cudaGetSymbolAddress((void**)&w3,  g_w3);
    cudaGetSymbolAddress((void**)&wxt, g_wxt);
    cudaGetSymbolAddress((void**)&hend,   g_hend);
    cudaGetSymbolAddress((void**)&hstart, g_hstart);
    cudaGetSymbolAddress((void**)&sdt,    g_sdt);

    cudaFuncSetAttribute(gemm_fp16<0>, cudaFuncAttributeMaxDynamicSharedMemorySize, GEMM_SMEM_BYTES);
    cudaFuncSetAttribute(gemm_fp16<1>, cudaFuncAttributeMaxDynamicSharedMemorySize, GEMM_SMEM_BYTES);
    cudaFuncSetAttribute(gemm_fp16<2>, cudaFuncAttributeMaxDynamicSharedMemorySize, GEMM_SMEM_BYTES);

    dim3 blk(256);

    // 0) fused prep: all fp16 conversions + W_xproj transpose
    prep_all<<<P_BLOCKS, 256>>>(x, W_in, W_dt, W_out, W_xp,
                                xh, w1, w2, w3, wxt);

    // 1) xz = x @ W_in + b_in; split+silu -> uh, szh (both half)
    gemm_fp16<0><<<dim3(4096 / 128, MM / 128), blk, GEMM_SMEM_BYTES>>>(
        xh, w1, b_in, nullptr, uh, szh, MM, 4096, DMODEL);

    // 2) xdbl = u @ W_xproj + b_xproj  (W^T path)
    xproj_kernel<<<MM / 8, 256>>>(uh, wxt, b_xp, xd);

    // 3) dt = softplus(u @ W_dt + b_dt)  (fp32 out)
    gemm_fp16<1><<<dim3(DINNER / 128, MM / 128), blk, GEMM_SMEM_BYTES>>>(
        uh, w2, b_dt, dtb, nullptr, nullptr, MM, DINNER, DINNER);

    // 4) chunked selective scan + fuse * silu(z) -> ym half
    scan_pass1<<<dim3(DINNER / 64, NCHUNK - 1, NBATCH), 256>>>(
        uh, dtb, xd, A_log, hend, sdt);
    scan_fix<<<NBATCH * DINNER * DSTATE / 256, 256>>>(A_log, hend, sdt, hstart);
    scan_pass2<<<dim3(DINNER / 64, NCHUNK, NBATCH), 256>>>(
        uh, dtb, xd, szh, A_log, D_par, hstart, ymh);

    // 5) out = ym @ W_out + b_out
    gemm_fp16<2><<<dim3(DMODEL / 128, MM / 128), blk, GEMM_SMEM_BYTES>>>(
        ymh, w3, b_out, out, nullptr, nullptr, MM, DMODEL, DINNER);
}

// round 16
// speedup vs baseline: 1.0254x; 1.0254x over previous
#include <cuda_runtime.h>
#include <cuda_fp16.h>
#include <mma.h>
#include <cstdint>

using namespace nvcuda;

// Problem constants
#define MM     8192      // BATCH*SEQ
#define DMODEL 1024
#define DINNER 2048
#define DSTATE 16
#define NBATCH 4
#define SEQLEN 2048
#define NCHUNK 8
#define CLEN   256       // SEQLEN / NCHUNK
#define NBLK   (CLEN / 32)

// ---------------- scratch (device globals: allocation-free) ----------------
__device__ __half g_uh [MM * DINNER];      // silu(x_proj) half
__device__ __half g_szh[MM * DINNER];      // silu(z) half
__device__ float  g_dt [MM * DINNER];      // softplus(dt) fp32 (exponent input)
__device__ float  g_xd [MM * 32];          // [B|C] projection
__device__ __half g_ymh[MM * DINNER];      // y * silu(z) half (out GEMM)
__device__ __half g_xh [MM * DMODEL];      // half x
__device__ __half g_w1 [DMODEL * 4096];    // half W_in
__device__ __half g_w2 [DINNER * DINNER];  // half W_dt
__device__ __half g_w3 [DINNER * DMODEL];  // half W_out
__device__ float  g_wxt[32 * DINNER];      // W_xproj^T fp32 [32][2048]
__device__ float  g_hend  [NBATCH * NCHUNK * DINNER * DSTATE];
__device__ float  g_hstart[NBATCH * NCHUNK * DINNER * DSTATE];
__device__ float  g_sdt   [NBATCH * NCHUNK * DINNER];

__device__ __forceinline__ float siluf(float v) { return v / (1.f + __expf(-v)); }
__device__ __forceinline__ float softplusf(float v) {
    return fmaxf(v, 0.f) + log1pf(__expf(-fabsf(v)));
}
__device__ __forceinline__ float ex2(float x) {
    float r; asm("ex2.approx.f32 %0, %1;" : "=f"(r) : "f"(x)); return r;
}

// ---------------- cp.async helpers ----------------------------------------
__device__ __forceinline__ void cp16(void* s, const void* g) {
    unsigned sa = (unsigned)__cvta_generic_to_shared(s);
    asm volatile("cp.async.cg.shared.global [%0], [%1], 16;\n" :: "r"(sa), "l"(g));
}
__device__ __forceinline__ void cp_commit() {
    asm volatile("cp.async.commit_group;\n" ::: "memory");
}
template<int N> __device__ __forceinline__ void cp_wait() {
    asm volatile("cp.async.wait_group %0;\n" :: "n"(N) : "memory");
}

// ---------------- fp16 WMMA GEMM (PROVEN R12 winner config, BK=32) ----------
// C = A[MxK] @ B[KxN] + bias (A,B half; accum fp32). 8 warps, warp tile
// 64x32, block tile 128x128x32, 2-stage cp.async. Epilogue reuses A region.
// EPI 0: silu; cols<2048 -> outh0 (half), else -> outh1 (half)
// EPI 1: softplus -> out0 f32
// EPI 2: plain    -> out0 f32
constexpr int AS_STRIDE = 40;
constexpr int BS_STRIDE = 136;
constexpr int AS_TILE   = 128 * AS_STRIDE;    // 5120 halves
constexpr int BS_TILE   = 32 * BS_STRIDE;     // 4352 halves
constexpr int GEMM_SMEM_BYTES = 2 * (AS_TILE + BS_TILE) * 2;   // 37888 B

template<int EPI>
__global__ __launch_bounds__(256) void gemm_fp16(
    const __half* __restrict__ A, const __half* __restrict__ B,
    const float* __restrict__ bias,
    float* __restrict__ out0, __half* __restrict__ outh0,
    __half* __restrict__ outh1,
    int M, int N, int K)
{
    extern __shared__ char smem[];
    __half* As = (__half*)smem;                       // [2][128][40]
    __half* Bs = (__half*)smem + 2 * AS_TILE;         // [2][32][136]
    float*  Epi = (float*)smem;                       // reused post-loop (8KB)

    const int tid  = threadIdx.x;
    const int wid  = tid >> 5;   // 0..7
    const int lane = tid & 31;
    const int wm   = wid >> 2;   // 0..1 -> 64-row half
    const int wn   = wid & 3;    // 0..3 -> 32-col quarter
    const int m0   = blockIdx.y * 128;
    const int n0   = blockIdx.x * 128;

    const int arow = tid >> 2;            // + r*64
    const int ac16 = tid & 3;
    const int brow = tid >> 4;            // + r*16
    const int bc16 = tid & 15;

    wmma::fragment<wmma::accumulator, 16, 16, 16, float> acc[4][2];
    #pragma unroll
    for (int i = 0; i < 4; i++)
        #pragma unroll
        for (int j = 0; j < 2; j++)
            wmma::fill_fragment(acc[i][j], 0.f);

    const int NIT = K >> 5;

    auto load_ab = [&](int buf, int k0) {
        __half* da = As + buf * AS_TILE;
        __half* db = Bs + buf * BS_TILE;
        #pragma unroll
        for (int r = 0; r < 2; r++) {
            int row = arow + r * 64;
            cp16(&da[row * AS_STRIDE + ac16 * 8],
                 &A[(size_t)(m0 + row) * K + k0 + ac16 * 8]);
        }
        #pragma unroll
        for (int r = 0; r < 2; r++) {
            int row = brow + r * 16;
            cp16(&db[row * BS_STRIDE + bc16 * 8],
                 &B[(size_t)(k0 + row) * N + n0 + bc16 * 8]);
        }
        cp_commit();
    };

    load_ab(0, 0);

    for (int it = 0; it < NIT; it++) {
        const int buf = it & 1;
        if (it + 1 < NIT) {
            load_ab(buf ^ 1, (it + 1) << 5);
            cp_wait<1>();
        } else {
            cp_wait<0>();
        }
        __syncthreads();

        const __half* ca = As + buf * AS_TILE;
        const __half* cb = Bs + buf * BS_TILE;
        #pragma unroll
        for (int kk = 0; kk < 32; kk += 16) {
            wmma::fragment<wmma::matrix_a, 16, 16, 16, __half, wmma::row_major> af[4];
            wmma::fragment<wmma::matrix_b, 16, 16, 16, __half, wmma::row_major> bf[2];
            #pragma unroll
            for (int i = 0; i < 4; i++)
                wmma::load_matrix_sync(af[i],
                    &ca[(wm * 64 + i * 16) * AS_STRIDE + kk], AS_STRIDE);
            #pragma unroll
            for (int j = 0; j < 2; j++)
                wmma::load_matrix_sync(bf[j],
                    &cb[kk * BS_STRIDE + wn * 32 + j * 16], BS_STRIDE);
            #pragma unroll
            for (int i = 0; i < 4; i++)
                #pragma unroll
                for (int j = 0; j < 2; j++)
                    wmma::mma_sync(acc[i][j], af[i], bf[j], acc[i][j]);
        }
        __syncthreads();
    }
    // last loop iteration ended with __syncthreads(): safe to reuse As as Epi

    float* EpiW = Epi + wid * 256;
    #pragma unroll
    for (int i = 0; i < 4; i++) {
        #pragma unroll
        for (int j = 0; j < 2; j++) {
            wmma::store_matrix_sync(EpiW, acc[i][j], 16, wmma::mem_row_major);
            __syncwarp();
            int gr0 = m0 + wm * 64 + i * 16;
            int gc0 = n0 + wn * 32 + j * 16;
            #pragma unroll
            for (int e = 0; e < 8; e++) {
                int idx = lane + e * 32;
                int r = idx >> 4, c = idx & 15;
                int gr = gr0 + r, gc = gc0 + c;
                float v = EpiW[r * 16 + c] + bias[gc];
                if (EPI == 0) {
                    float sv = siluf(v);
                    if (gc < DINNER)
                        outh0[(size_t)gr * DINNER + gc] = __float2half(sv);
                    else
                        outh1[(size_t)gr * DINNER + gc - DINNER] = __float2half(sv);
                } else if (EPI == 1) {
                    out0[(size_t)gr * DINNER + gc] = softplusf(v);
                } else {
                    out0[(size_t)gr * (size_t)N + gc] = v;
                }
            }
            __syncwarp();
        }
    }
}

// ---------------- split prep -------------------------------------------------
__device__ __forceinline__ void half8(const float* __restrict__ src,
                                      __half* __restrict__ dst, long u)
{
    long i = u * 8;
    float4 a = *(const float4*)&src[i];
    float4 b = *(const float4*)&src[i + 4];
    __half2 h[4];
    h[0] = __floats2half2_rn(a.x, a.y);
    h[1] = __floats2half2_rn(a.z, a.w);
    h[2] = __floats2half2_rn(b.x, b.y);
    h[3] = __floats2half2_rn(b.z, b.w);
    *(uint4*)&dst[i] = *(uint4*)h;
}

// prep_x: x (1048576 units) + W_in (524288 units) -> needed by GEMM1
#define PX_S0 1048576
#define PX_S1 (PX_S0 + 524288)
#define PX_BLOCKS (PX_S1 / 256)     // 6144
__global__ __launch_bounds__(256) void prep_x(
    const float* __restrict__ x, const float* __restrict__ W_in,
    __half* __restrict__ xh, __half* __restrict__ w1)
{
    long u = (long)blockIdx.x * 256 + threadIdx.x;
    if (u < PX_S0) half8(x, xh, u);
    else           half8(W_in, w1, u - PX_S0);
}

// prep_w: W_dt (524288) + W_out (262144) + W_xproj^T (16384 units of 4)
#define PW_S0 524288
#define PW_S1 (PW_S0 + 262144)
#define PW_S2 (PW_S1 + 16384)
#define PW_BLOCKS (PW_S2 / 256)     // 3136
__global__ __launch_bounds__(256) void prep_w(
    const float* __restrict__ W_dt, const float* __restrict__ W_out,
    const float* __restrict__ W_xp,
    __half* __restrict__ w2, __half* __restrict__ w3,
    float* __restrict__ wxt)
{
    long u = (long)blockIdx.x * 256 + threadIdx.x;
    if (u < PW_S0)      half8(W_dt,  w2, u);
    else if (u < PW_S1) half8(W_out, w3, u - PW_S0);
    else {
        long j = u - PW_S1;           // 16384 units: WT[c][k0..k0+3]
        int c  = (int)(j & 31);
        int k0 = (int)(j >> 5) * 4;
        float4 v;
        v.x = W_xp[(size_t)(k0 + 0) * 32 + c];
        v.y = W_xp[(size_t)(k0 + 1) * 32 + c];
        v.z = W_xp[(size_t)(k0 + 2) * 32 + c];
        v.w = W_xp[(size_t)(k0 + 3) * 32 + c];
        *(float4*)&wxt[(size_t)c * DINNER + k0] = v;
    }
}

// ---------------- skinny projection: xdbl = u @ W_xproj + b ----------------
__global__ __launch_bounds__(256) void xproj_kernel(
    const __half* __restrict__ uh, const float* __restrict__ WT,
    const float* __restrict__ bias, float* __restrict__ xdbl)
{
    __shared__ __align__(16) float WTs[32][68];
    __shared__ __align__(16) float Us[8][64];

    const int tid  = threadIdx.x;
    const int wid  = tid >> 5;     // row within block (0..7)
    const int lane = tid & 31;     // output column
    const size_t row = (size_t)blockIdx.x * 8 + wid;

    float acc = 0.f;
    for (int k0 = 0; k0 < DINNER; k0 += 64) {
        {
            int c = tid >> 3, kk = (tid & 7) * 8;
            float4 a = *(const float4*)&WT[(size_t)c * DINNER + k0 + kk];
            float4 b = *(const float4*)&WT[(size_t)c * DINNER + k0 + kk + 4];
            *(float4*)&WTs[c][kk]     = a;
            *(float4*)&WTs[c][kk + 4] = b;
        }
        if (tid < 64) {
            int r = tid >> 3, kk = (tid & 7) * 8;
            const __half* up =
                &uh[((size_t)blockIdx.x * 8 + r) * DINNER + k0 + kk];
            float4 f0, f1;
            f0.x = __half2float(up[0]); f0.y = __half2float(up[1]);
            f0.z = __half2float(up[2]); f0.w = __half2float(up[3]);
            f1.x = __half2float(up[4]); f1.y = __half2float(up[5]);
            f1.z = __half2float(up[6]); f1.w = __half2float(up[7]);
            *(float4*)&Us[r][kk]     = f0;
            *(float4*)&Us[r][kk + 4] = f1;
        }
        __syncthreads();

        #pragma unroll
        for (int kk = 0; kk < 64; kk += 4) {
            float4 w  = *(const float4*)&WTs[lane][kk];
            float4 uu = *(const float4*)&Us[wid][kk];
            acc = fmaf(uu.x, w.x, acc);
            acc = fmaf(uu.y, w.y, acc);
            acc = fmaf(uu.z, w.z, acc);
            acc = fmaf(uu.w, w.w, acc);
        }
        __syncthreads();
    }
    xdbl[row * 32 + lane] = acc + bias[lane];
}

// ---------------- chunked selective scan (software-pipelined staging) -------
// Pass 1: local recurrence h0=0 -> h_end, sum(dt).
__global__ __launch_bounds__(256) void scan_pass1(
    const __half* __restrict__ uh, const float* __restrict__ dt,
    const float* __restrict__ xdbl, const float* __restrict__ A_log,
    float* __restrict__ hend, float* __restrict__ sdtg)
{
    __shared__ __half Uh[2][32][64];
    __shared__ float  Dt[2][32][64];
    __shared__ float  XD[2][32][32];

    const int b    = blockIdx.z;
    const int c    = blockIdx.y;
    const int d0   = blockIdx.x * 64;
    const int tid  = threadIdx.x;
    const int wid  = tid >> 5;
    const int lane = tid & 31;
    const int dq   = lane >> 2;
    const int sq   = lane & 3;
    const int dl   = wid * 8 + dq;
    const int d    = d0 + dl;

    float Ap[4], h[4] = {0.f, 0.f, 0.f, 0.f};
    #pragma unroll
    for (int i = 0; i < 4; i++)
        Ap[i] = -__expf(A_log[d * DSTATE + sq * 4 + i]) * 1.4426950408889634f;
    float sdt = 0.f;
    const size_t base = (size_t)b * SEQLEN * DINNER;
    const int tstart = c * CLEN;

    const int ut_t = tid >> 3, ut_g = tid & 7;
    const int xd_t = tid >> 3, xd_g = tid & 7;

    uint4  uReg;
    float4 dReg0, dReg1;
    float4 xReg;

    auto ldg_block = [&](int t0) {
        uReg = *(const uint4*)&uh[base + (size_t)(t0 + ut_t) * DINNER + d0 + ut_g * 8];
        {
            int tt = tid >> 4, gg = tid & 15;
            dReg0 = *(const float4*)&dt[base + (size_t)(t0 + tt) * DINNER + d0 + gg * 4];
            int idx = tid + 256; tt = idx >> 4; gg = idx & 15;
            dReg1 = *(const float4*)&dt[base + (size_t)(t0 + tt) * DINNER + d0 + gg * 4];
        }
        xReg = *(const float4*)&xdbl[((size_t)b * SEQLEN + t0 + xd_t) * 32 + xd_g * 4];
    };
    auto sts_block = [&](int bf) {
        *(uint4*)&Uh[bf][ut_t][ut_g * 8] = uReg;
        {
            int tt = tid >> 4, gg = tid & 15;
            *(float4*)&Dt[bf][tt][gg * 4] = dReg0;
            int idx = tid + 256; tt = idx >> 4; gg = idx & 15;
            *(float4*)&Dt[bf][tt][gg * 4] = dReg1;
        }
        *(float4*)&XD[bf][xd_t][xd_g * 4] = xReg;
    };

    ldg_block(tstart);
    sts_block(0);
    __syncthreads();

    for (int blk = 0; blk < NBLK; blk++) {
        const int bf = blk & 1;
        const bool more = (blk + 1 < NBLK);
        if (more) ldg_block(tstart + (blk + 1) * 32);

        #pragma unroll 4
        for (int t = 0; t < 32; t++) {
            float uv  = __half2float(Uh[bf][t][dl]);
            float dtv = Dt[bf][t][dl];
            float4 Bv = *(const float4*)&XD[bf][t][sq * 4];
            float du  = dtv * uv;
            sdt += dtv;
            h[0] = fmaf(h[0], ex2(dtv * Ap[0]), du * Bv.x);
            h[1] = fmaf(h[1], ex2(dtv * Ap[1]), du * Bv.y);
            h[2] = fmaf(h[2], ex2(dtv * Ap[2]), du * Bv.z);
            h[3] = fmaf(h[3], ex2(dtv * Ap[3]), du * Bv.w);
        }
        if (more) sts_block(bf ^ 1);
        __syncthreads();
    }

    size_t ho = ((size_t)(b * NCHUNK + c) * DINNER + d) * DSTATE + sq * 4;
    *(float4*)&hend[ho] = make_float4(h[0], h[1], h[2], h[3]);
    if (sq == 0) sdtg[(size_t)(b * NCHUNK + c) * DINNER + d] = sdt;
}

// Fix: sequential chain over chunks. thread = one (b,d,s).
__global__ __launch_bounds__(256) void scan_fix(
    const float* __restrict__ A_log, const float* __restrict__ hend,
    const float* __restrict__ sdtg, float* __restrict__ hstart)
{
    int idx = blockIdx.x * 256 + threadIdx.x;
    int s = idx & 15;
    int d = (idx >> 4) & (DINNER - 1);
    int b = idx >> 15;
    float Ap = -__expf(A_log[d * DSTATE + s]) * 1.4426950408889634f;
    float hs = 0.f;
    hstart[((size_t)(b * NCHUNK) * DINNER + d) * DSTATE + s] = 0.f;
    #pragma unroll
    for (int c = 1; c < NCHUNK; c++) {
        size_t pc = (size_t)(b * NCHUNK + c - 1) * DINNER + d;
        float P = ex2(Ap * sdtg[pc]);
        hs = fmaf(P, hs, hend[pc * DSTATE + s]);
        hstart[((size_t)(b * NCHUNK + c) * DINNER + d) * DSTATE + s] = hs;
    }
}

// Pass 2: full scan within chunk, seeded with h_start; fused * silu(z).
__global__ __launch_bounds__(256) void scan_pass2(
    const __half* __restrict__ uh, const float* __restrict__ dt,
    const float* __restrict__ xdbl, const __half* __restrict__ szh,
    const float* __restrict__ A_log, const float* __restrict__ Dp,
    const float* __restrict__ hstart, __half* __restrict__ ymh)
{
    __shared__ __half Uh[2][32][64];
    __shared__ float  Dt[2][32][64];
    __shared__ __half Sz[2][32][64];
    __shared__ float  XD[2][32][32];

    const int b    = blockIdx.z;
    const int c    = blockIdx.y;
    const int d0   = blockIdx.x * 64;
    const int tid  = threadIdx.x;
    const int wid  = tid >> 5;
    const int lane = tid & 31;
    const int dq   = lane >> 2;
    const int sq   = lane & 3;
    const int dl   = wid * 8 + dq;
    const int d    = d0 + dl;

    float Ap[4], h[4];
    #pragma unroll
    for (int i = 0; i < 4; i++)
        Ap[i] = -__expf(A_log[d * DSTATE + sq * 4 + i]) * 1.4426950408889634f;
    {
        float4 h0 = *(const float4*)
            &hstart[((size_t)(b * NCHUNK + c) * DINNER + d) * DSTATE + sq * 4];
        h[0] = h0.x; h[1] = h0.y; h[2] = h0.z; h[3] = h0.w;
    }
    const float Dv = Dp[d];
    const size_t base = (size_t)b * SEQLEN * DINNER;
    const int tstart = c * CLEN;

    const int ut_t = tid >> 3, ut_g = tid & 7;
    const int xd_t = tid >> 3, xd_g = tid & 7;

    uint4  uReg, zReg;
    float4 dReg0, dReg1;
    float4 xReg;

    auto ldg_block = [&](int t0) {
        size_t go = base + (size_t)(t0 + ut_t) * DINNER + d0 + ut_g * 8;
        uReg = *(const uint4*)&uh[go];
        zReg = *(const uint4*)&szh[go];
        {
            int tt = tid >> 4, gg = tid & 15;
            dReg0 = *(const float4*)&dt[base + (size_t)(t0 + tt) * DINNER + d0 + gg * 4];
            int idx = tid + 256; tt = idx >> 4; gg = idx & 15;
            dReg1 = *(const float4*)&dt[base + (size_t)(t0 + tt) * DINNER + d0 + gg * 4];
        }
        xReg = *(const float4*)&xdbl[((size_t)b * SEQLEN + t0 + xd_t) * 32 + xd_g * 4];
    };
    auto sts_block = [&](int bf) {
        *(uint4*)&Uh[bf][ut_t][ut_g * 8] = uReg;
        *(uint4*)&Sz[bf][ut_t][ut_g * 8] = zReg;
        {
            int tt = tid >> 4, gg = tid & 15;
            *(float4*)&Dt[bf][tt][gg * 4] = dReg0;
            int idx = tid + 256; tt = idx >> 4; gg = idx & 15;
            *(float4*)&Dt[bf][tt][gg * 4] = dReg1;
        }
        *(float4*)&XD[bf][xd_t][xd_g * 4] = xReg;
    };

    ldg_block(tstart);
    sts_block(0);
    __syncthreads();

    for (int blk = 0; blk < NBLK; blk++) {
        const int bf = blk & 1;
        const bool more = (blk + 1 < NBLK);
        const int t0 = tstart + blk * 32;
        if (more) ldg_block(t0 + 32);

        #pragma unroll 4
        for (int t = 0; t < 32; t++) {
            float uv  = __half2float(Uh[bf][t][dl]);
            float dtv = Dt[bf][t][dl];
            float4 Bv = *(const float4*)&XD[bf][t][sq * 4];
            float4 Cv = *(const float4*)&XD[bf][t][16 + sq * 4];
            float du  = dtv * uv;
            float p;
            h[0] = fmaf(h[0], ex2(dtv * Ap[0]), du * Bv.x);
            h[1] = fmaf(h[1], ex2(dtv * Ap[1]), du * Bv.y);
            h[2] = fmaf(h[2], ex2(dtv * Ap[2]), du * Bv.z);
            h[3] = fmaf(h[3], ex2(dtv * Ap[3]), du * Bv.w);
            p  = h[0] * Cv.x;
            p  = fmaf(h[1], Cv.y, p);
            p  = fmaf(h[2], Cv.z, p);
            p  = fmaf(h[3], Cv.w, p);
            p += __shfl_xor_sync(0xffffffffu, p, 1);
            p += __shfl_xor_sync(0xffffffffu, p, 2);
            if (sq == 0) {
                float zv = __half2float(Sz[bf][t][dl]);
                float y  = fmaf(Dv, uv, p);
                ymh[base + (size_t)(t0 + t) * DINNER + d] = __float2half(y * zv);
            }
        }
        if (more) sts_block(bf ^ 1);
        __syncthreads();
    }
}

// ---------------- launch ---------------------------------------------------
extern "C" void kernel_launch(void* const* d_in, const int* in_sizes, int n_in,
                              void* d_out, int out_size)
{
    const float* x     = (const float*)d_in[0];
    const float* W_in  = (const float*)d_in[1];
    const float* b_in  = (const float*)d_in[2];
    const float* W_xp  = (const float*)d_in[3];
    const float* b_xp  = (const float*)d_in[4];
    const float* W_dt  = (const float*)d_in[5];
    const float* b_dt  = (const float*)d_in[6];
    const float* W_out = (const float*)d_in[7];
    const float* b_out = (const float*)d_in[8];
    const float* A_log = (const float*)d_in[9];
    const float* D_par = (const float*)d_in[10];
    float* out = (float*)d_out;

    float *dtb, *xd, *wxt, *hend, *hstart, *sdt;
    __half *uh, *szh, *ymh, *xh, *w1, *w2, *w3;
    cudaGetSymbolAddress((void**)&uh,  g_uh);
    cudaGetSymbolAddress((void**)&szh, g_szh);
    cudaGetSymbolAddress((void**)&dtb, g_dt);
    cudaGetSymbolAddress((void**)&xd,  g_xd);
    cudaGetSymbolAddress((void**)&ymh, g_ymh);
    cudaGetSymbolAddress((void**)&xh,  g_xh);
    cudaGetSymbolAddress((void**)&w1,  g_w1);
    cudaGetSymbolAddress((void**)&w2,  g_w2);
    cudaGetSymbolAddress((void**)&w3,  g_w3);
    cudaGetSymbolAddress((void**)&wxt, g_wxt);
    cudaGetSymbolAddress((void**)&hend,   g_hend);
    cudaGetSymbolAddress((void**)&hstart, g_hstart);
    cudaGetSymbolAddress((void**)&sdt,    g_sdt);

    cudaFuncSetAttribute(gemm_fp16<0>, cudaFuncAttributeMaxDynamicSharedMemorySize, GEMM_SMEM_BYTES);
    cudaFuncSetAttribute(gemm_fp16<1>, cudaFuncAttributeMaxDynamicSharedMemorySize, GEMM_SMEM_BYTES);
    cudaFuncSetAttribute(gemm_fp16<2>, cudaFuncAttributeMaxDynamicSharedMemorySize, GEMM_SMEM_BYTES);

    // side stream + fork/join events (host handles only; created per call,
    // referenced by the captured graph — replay re-uses the graph nodes)
    cudaStream_t s2;
    cudaStreamCreateWithFlags(&s2, cudaStreamNonBlocking);
    cudaEvent_t eA, eP, eB, eX;
    cudaEventCreateWithFlags(&eA, cudaEventDisableTiming);
    cudaEventCreateWithFlags(&eP, cudaEventDisableTiming);
    cudaEventCreateWithFlags(&eB, cudaEventDisableTiming);
    cudaEventCreateWithFlags(&eX, cudaEventDisableTiming);

    dim3 blk(256);

    // 0a) prep x + W_in (needed by GEMM1) on main stream
    prep_x<<<PX_BLOCKS, 256>>>(x, W_in, xh, w1);
    cudaEventRecord(eA, 0);
    // 0b) prep W_dt/W_out/W_xp^T on s2, overlapping GEMM1
    cudaStreamWaitEvent(s2, eA, 0);
    prep_w<<<PW_BLOCKS, 256, 0, s2>>>(W_dt, W_out, W_xp, w2, w3, wxt);
    cudaEventRecord(eP, s2);

    // 1) xz = x @ W_in + b_in; split+silu -> uh, szh (both half)
    gemm_fp16<0><<<dim3(4096 / 128, MM / 128), blk, GEMM_SMEM_BYTES>>>(
        xh, w1, b_in, nullptr, uh, szh, MM, 4096, DMODEL);
    cudaEventRecord(eB, 0);

    // 2) xdbl = u @ W_xproj + b_xproj on s2, overlapping GEMM2
    //    (s2 already ordered after prep_w -> wxt ready)
    cudaStreamWaitEvent(s2, eB, 0);
    xproj_kernel<<<MM / 8, 256, 0, s2>>>(uh, wxt, b_xp, xd);
    cudaEventRecord(eX, s2);

    // 3) dt = softplus(u @ W_dt + b_dt) on main (needs w2 from prep_w)
    cudaStreamWaitEvent(0, eP, 0);
    gemm_fp16<1><<<dim3(DINNER / 128, MM / 128), blk, GEMM_SMEM_BYTES>>>(
        uh, w2, b_dt, dtb, nullptr, nullptr, MM, DINNER, DINNER);

    // join: scan needs xd from s2
    cudaStreamWaitEvent(0, eX, 0);

    // 4) chunked selective scan + fuse * silu(z) -> ym half
    scan_pass1<<<dim3(DINNER / 64, NCHUNK - 1, NBATCH), 256>>>(
        uh, dtb, xd, A_log, hend, sdt);
    scan_fix<<<NBATCH * DINNER * DSTATE / 256, 256>>>(A_log, hend, sdt, hstart);
    scan_pass2<<<dim3(DINNER / 64, NCHUNK, NBATCH), 256>>>(
        uh, dtb, xd, szh, A_log, D_par, hstart, ymh);

    // 5) out = ym @ W_out + b_out
    gemm_fp16<2><<<dim3(DMODEL / 128, MM / 128), blk, GEMM_SMEM_BYTES>>>(
        ymh, w3, b_out, out, nullptr, nullptr, MM, DMODEL, DINNER);
}

// round 17
// speedup vs baseline: 1.1668x; 1.1378x over previous
#include <cuda_runtime.h>
#include <cuda_fp16.h>
#include <mma.h>
#include <cstdint>

using namespace nvcuda;

// Problem constants
#define MM     8192      // BATCH*SEQ
#define DMODEL 1024
#define DINNER 2048
#define DSTATE 16
#define NBATCH 4
#define SEQLEN 2048
#define NCHUNK 8
#define CLEN   256       // SEQLEN / NCHUNK
#define NBLK   (CLEN / 32)

// ---------------- scratch (device globals: allocation-free) ----------------
__device__ __half g_uh  [MM * DINNER];      // silu(x_proj) half
__device__ __half g_szh [MM * DINNER];      // silu(z) half
__device__ float  g_dt  [MM * DINNER];      // softplus(dt) fp32
__device__ float  g_xd  [MM * 32];          // [B|C] projection
__device__ __half g_ymh [MM * DINNER];      // y * silu(z) half
__device__ __half g_xh  [MM * DMODEL];      // half x
__device__ __half g_w1  [DMODEL * 4096];    // half W_in
__device__ __half g_w2  [DINNER * DINNER];  // half W_dt
__device__ __half g_w3  [DINNER * DMODEL];  // half W_out
__device__ __half g_wxph[DINNER * 128];     // half W_xproj padded [2048][128]
__device__ float  g_hend  [NBATCH * NCHUNK * DINNER * DSTATE];
__device__ float  g_hstart[NBATCH * NCHUNK * DINNER * DSTATE];
__device__ float  g_sdt   [NBATCH * NCHUNK * DINNER];

__device__ __forceinline__ float siluf(float v) { return v / (1.f + __expf(-v)); }
__device__ __forceinline__ float softplusf(float v) {
    return fmaxf(v, 0.f) + log1pf(__expf(-fabsf(v)));
}
__device__ __forceinline__ float ex2(float x) {
    float r; asm("ex2.approx.f32 %0, %1;" : "=f"(r) : "f"(x)); return r;
}

// ---------------- cp.async helpers ----------------------------------------
__device__ __forceinline__ void cp16(void* s, const void* g) {
    unsigned sa = (unsigned)__cvta_generic_to_shared(s);
    asm volatile("cp.async.cg.shared.global [%0], [%1], 16;\n" :: "r"(sa), "l"(g));
}
__device__ __forceinline__ void cp_commit() {
    asm volatile("cp.async.commit_group;\n" ::: "memory");
}
template<int N> __device__ __forceinline__ void cp_wait() {
    asm volatile("cp.async.wait_group %0;\n" :: "n"(N) : "memory");
}

// ---------------- fp16 WMMA GEMM (PROVEN R12 winner config, BK=32) ----------
// C = A[MxK] @ B[KxN] + bias (A,B half; accum fp32). 8 warps, warp tile
// 64x32, block tile 128x128x32, 2-stage cp.async. Epilogue reuses A region.
// EPI 0: silu; cols<2048 -> outh0 (half), else -> outh1 (half)
// EPI 1: softplus -> out0 f32
// EPI 2: plain    -> out0 f32
// EPI 3: xproj: only gc<32 valid -> out0[gr*32+gc] f32 (+bias[gc])
constexpr int AS_STRIDE = 40;
constexpr int BS_STRIDE = 136;
constexpr int AS_TILE   = 128 * AS_STRIDE;    // 5120 halves
constexpr int BS_TILE   = 32 * BS_STRIDE;     // 4352 halves
constexpr int GEMM_SMEM_BYTES = 2 * (AS_TILE + BS_TILE) * 2;   // 37888 B

template<int EPI>
__global__ __launch_bounds__(256) void gemm_fp16(
    const __half* __restrict__ A, const __half* __restrict__ B,
    const float* __restrict__ bias,
    float* __restrict__ out0, __half* __restrict__ outh0,
    __half* __restrict__ outh1,
    int M, int N, int K)
{
    extern __shared__ char smem[];
    __half* As = (__half*)smem;                       // [2][128][40]
    __half* Bs = (__half*)smem + 2 * AS_TILE;         // [2][32][136]
    float*  Epi = (float*)smem;                       // reused post-loop (8KB)

    const int tid  = threadIdx.x;
    const int wid  = tid >> 5;   // 0..7
    const int lane = tid & 31;
    const int wm   = wid >> 2;   // 0..1 -> 64-row half
    const int wn   = wid & 3;    // 0..3 -> 32-col quarter
    const int m0   = blockIdx.y * 128;
    const int n0   = blockIdx.x * 128;

    const int arow = tid >> 2;            // + r*64
    const int ac16 = tid & 3;
    const int brow = tid >> 4;            // + r*16
    const int bc16 = tid & 15;

    wmma::fragment<wmma::accumulator, 16, 16, 16, float> acc[4][2];
    #pragma unroll
    for (int i = 0; i < 4; i++)
        #pragma unroll
        for (int j = 0; j < 2; j++)
            wmma::fill_fragment(acc[i][j], 0.f);

    const int NIT = K >> 5;

    auto load_ab = [&](int buf, int k0) {
        __half* da = As + buf * AS_TILE;
        __half* db = Bs + buf * BS_TILE;
        #pragma unroll
        for (int r = 0; r < 2; r++) {
            int row = arow + r * 64;
            cp16(&da[row * AS_STRIDE + ac16 * 8],
                 &A[(size_t)(m0 + row) * K + k0 + ac16 * 8]);
        }
        #pragma unroll
        for (int r = 0; r < 2; r++) {
            int row = brow + r * 16;
            cp16(&db[row * BS_STRIDE + bc16 * 8],
                 &B[(size_t)(k0 + row) * N + n0 + bc16 * 8]);
        }
        cp_commit();
    };

    load_ab(0, 0);

    for (int it = 0; it < NIT; it++) {
        const int buf = it & 1;
        if (it + 1 < NIT) {
            load_ab(buf ^ 1, (it + 1) << 5);
            cp_wait<1>();
        } else {
            cp_wait<0>();
        }
        __syncthreads();

        const __half* ca = As + buf * AS_TILE;
        const __half* cb = Bs + buf * BS_TILE;
        #pragma unroll
        for (int kk = 0; kk < 32; kk += 16) {
            wmma::fragment<wmma::matrix_a, 16, 16, 16, __half, wmma::row_major> af[4];
            wmma::fragment<wmma::matrix_b, 16, 16, 16, __half, wmma::row_major> bf[2];
            #pragma unroll
            for (int i = 0; i < 4; i++)
                wmma::load_matrix_sync(af[i],
                    &ca[(wm * 64 + i * 16) * AS_STRIDE + kk], AS_STRIDE);
            #pragma unroll
            for (int j = 0; j < 2; j++)
                wmma::load_matrix_sync(bf[j],
                    &cb[kk * BS_STRIDE + wn * 32 + j * 16], BS_STRIDE);
            #pragma unroll
            for (int i = 0; i < 4; i++)
                #pragma unroll
                for (int j = 0; j < 2; j++)
                    wmma::mma_sync(acc[i][j], af[i], bf[j], acc[i][j]);
        }
        __syncthreads();
    }
    // last loop iteration ended with __syncthreads(): safe to reuse As as Epi

    float* EpiW = Epi + wid * 256;
    #pragma unroll
    for (int i = 0; i < 4; i++) {
        #pragma unroll
        for (int j = 0; j < 2; j++) {
            if (EPI == 3 && wn * 32 + j * 16 >= 32) continue;  // cols >= 32 unused
            wmma::store_matrix_sync(EpiW, acc[i][j], 16, wmma::mem_row_major);
            __syncwarp();
            int gr0 = m0 + wm * 64 + i * 16;
            int gc0 = n0 + wn * 32 + j * 16;
            #pragma unroll
            for (int e = 0; e < 8; e++) {
                int idx = lane + e * 32;
                int r = idx >> 4, c = idx & 15;
                int gr = gr0 + r, gc = gc0 + c;
                if (EPI == 3) {
                    if (gc < 32) {
                        float v = EpiW[r * 16 + c] + bias[gc];
                        out0[(size_t)gr * 32 + gc] = v;
                    }
                } else {
                    float v = EpiW[r * 16 + c] + bias[gc];
                    if (EPI == 0) {
                        float sv = siluf(v);
                        if (gc < DINNER)
                            outh0[(size_t)gr * DINNER + gc] = __float2half(sv);
                        else
                            outh1[(size_t)gr * DINNER + gc - DINNER] = __float2half(sv);
                    } else if (EPI == 1) {
                        out0[(size_t)gr * DINNER + gc] = softplusf(v);
                    } else {
                        out0[(size_t)gr * (size_t)N + gc] = v;
                    }
                }
            }
            __syncwarp();
        }
    }
}

// ---------------- split prep -------------------------------------------------
__device__ __forceinline__ void half8(const float* __restrict__ src,
                                      __half* __restrict__ dst, long u)
{
    long i = u * 8;
    float4 a = *(const float4*)&src[i];
    float4 b = *(const float4*)&src[i + 4];
    __half2 h[4];
    h[0] = __floats2half2_rn(a.x, a.y);
    h[1] = __floats2half2_rn(a.z, a.w);
    h[2] = __floats2half2_rn(b.x, b.y);
    h[3] = __floats2half2_rn(b.z, b.w);
    *(uint4*)&dst[i] = *(uint4*)h;
}

// prep_x: x (1048576 units) + W_in (524288 units) -> needed by GEMM1
#define PX_S0 1048576
#define PX_S1 (PX_S0 + 524288)
#define PX_BLOCKS (PX_S1 / 256)     // 6144
__global__ __launch_bounds__(256) void prep_x(
    const float* __restrict__ x, const float* __restrict__ W_in,
    __half* __restrict__ xh, __half* __restrict__ w1)
{
    long u = (long)blockIdx.x * 256 + threadIdx.x;
    if (u < PX_S0) half8(x, xh, u);
    else           half8(W_in, w1, u - PX_S0);
}

// prep_w: W_dt (524288) + W_out (262144) + W_xproj padded half (32768 units)
#define PW_S0 524288
#define PW_S1 (PW_S0 + 262144)
#define PW_S2 (PW_S1 + 32768)
#define PW_BLOCKS (PW_S2 / 256)     // 3200
__global__ __launch_bounds__(256) void prep_w(
    const float* __restrict__ W_dt, const float* __restrict__ W_out,
    const float* __restrict__ W_xp,
    __half* __restrict__ w2, __half* __restrict__ w3,
    __half* __restrict__ wxph)
{
    long u = (long)blockIdx.x * 256 + threadIdx.x;
    if (u < PW_S0)      half8(W_dt,  w2, u);
    else if (u < PW_S1) half8(W_out, w3, u - PW_S0);
    else {
        long j = u - PW_S1;           // 32768 units: wxph[k][c0..c0+7]
        int k  = (int)(j >> 4);
        int c0 = (int)(j & 15) * 8;
        __half hv[8];
        #pragma unroll
        for (int i = 0; i < 8; i++) {
            int c = c0 + i;
            hv[i] = (c < 32) ? __float2half(W_xp[(size_t)k * 32 + c])
                             : __float2half(0.f);
        }
        *(uint4*)&wxph[(size_t)k * 128 + c0] = *(uint4*)hv;
    }
}

// ---------------- chunked selective scan (software-pipelined staging) -------
// Pass 1: local recurrence h0=0 -> h_end, sum(dt).
__global__ __launch_bounds__(256) void scan_pass1(
    const __half* __restrict__ uh, const float* __restrict__ dt,
    const float* __restrict__ xdbl, const float* __restrict__ A_log,
    float* __restrict__ hend, float* __restrict__ sdtg)
{
    __shared__ __half Uh[2][32][64];
    __shared__ float  Dt[2][32][64];
    __shared__ float  XD[2][32][32];

    const int b    = blockIdx.z;
    const int c    = blockIdx.y;
    const int d0   = blockIdx.x * 64;
    const int tid  = threadIdx.x;
    const int wid  = tid >> 5;
    const int lane = tid & 31;
    const int dq   = lane >> 2;
    const int sq   = lane & 3;
    const int dl   = wid * 8 + dq;
    const int d    = d0 + dl;

    float Ap[4], h[4] = {0.f, 0.f, 0.f, 0.f};
    #pragma unroll
    for (int i = 0; i < 4; i++)
        Ap[i] = -__expf(A_log[d * DSTATE + sq * 4 + i]) * 1.4426950408889634f;
    float sdt = 0.f;
    const size_t base = (size_t)b * SEQLEN * DINNER;
    const int tstart = c * CLEN;

    const int ut_t = tid >> 3, ut_g = tid & 7;
    const int xd_t = tid >> 3, xd_g = tid & 7;

    uint4  uReg;
    float4 dReg0, dReg1;
    float4 xReg;

    auto ldg_block = [&](int t0) {
        uReg = *(const uint4*)&uh[base + (size_t)(t0 + ut_t) * DINNER + d0 + ut_g * 8];
        {
            int tt = tid >> 4, gg = tid & 15;
            dReg0 = *(const float4*)&dt[base + (size_t)(t0 + tt) * DINNER + d0 + gg * 4];
            int idx = tid + 256; tt = idx >> 4; gg = idx & 15;
            dReg1 = *(const float4*)&dt[base + (size_t)(t0 + tt) * DINNER + d0 + gg * 4];
        }
        xReg = *(const float4*)&xdbl[((size_t)b * SEQLEN + t0 + xd_t) * 32 + xd_g * 4];
    };
    auto sts_block = [&](int bf) {
        *(uint4*)&Uh[bf][ut_t][ut_g * 8] = uReg;
        {
            int tt = tid >> 4, gg = tid & 15;
            *(float4*)&Dt[bf][tt][gg * 4] = dReg0;
            int idx = tid + 256; tt = idx >> 4; gg = idx & 15;
            *(float4*)&Dt[bf][tt][gg * 4] = dReg1;
        }
        *(float4*)&XD[bf][xd_t][xd_g * 4] = xReg;
    };

    ldg_block(tstart);
    sts_block(0);
    __syncthreads();

    for (int blk = 0; blk < NBLK; blk++) {
        const int bf = blk & 1;
        const bool more = (blk + 1 < NBLK);
        if (more) ldg_block(tstart + (blk + 1) * 32);

        #pragma unroll 4
        for (int t = 0; t < 32; t++) {
            float uv  = __half2float(Uh[bf][t][dl]);
            float dtv = Dt[bf][t][dl];
            float4 Bv = *(const float4*)&XD[bf][t][sq * 4];
            float du  = dtv * uv;
            sdt += dtv;
            h[0] = fmaf(h[0], ex2(dtv * Ap[0]), du * Bv.x);
            h[1] = fmaf(h[1], ex2(dtv * Ap[1]), du * Bv.y);
            h[2] = fmaf(h[2], ex2(dtv * Ap[2]), du * Bv.z);
            h[3] = fmaf(h[3], ex2(dtv * Ap[3]), du * Bv.w);
        }
        if (more) sts_block(bf ^ 1);
        __syncthreads();
    }

    size_t ho = ((size_t)(b * NCHUNK + c) * DINNER + d) * DSTATE + sq * 4;
    *(float4*)&hend[ho] = make_float4(h[0], h[1], h[2], h[3]);
    if (sq == 0) sdtg[(size_t)(b * NCHUNK + c) * DINNER + d] = sdt;
}

// Fix: sequential chain over chunks. thread = one (b,d,s).
__global__ __launch_bounds__(256) void scan_fix(
    const float* __restrict__ A_log, const float* __restrict__ hend,
    const float* __restrict__ sdtg, float* __restrict__ hstart)
{
    int idx = blockIdx.x * 256 + threadIdx.x;
    int s = idx & 15;
    int d = (idx >> 4) & (DINNER - 1);
    int b = idx >> 15;
    float Ap = -__expf(A_log[d * DSTATE + s]) * 1.4426950408889634f;
    float hs = 0.f;
    hstart[((size_t)(b * NCHUNK) * DINNER + d) * DSTATE + s] = 0.f;
    #pragma unroll
    for (int c = 1; c < NCHUNK; c++) {
        size_t pc = (size_t)(b * NCHUNK + c - 1) * DINNER + d;
        float P = ex2(Ap * sdtg[pc]);
        hs = fmaf(P, hs, hend[pc * DSTATE + s]);
        hstart[((size_t)(b * NCHUNK + c) * DINNER + d) * DSTATE + s] = hs;
    }
}

// Pass 2: full scan within chunk, seeded with h_start; fused * silu(z).
__global__ __launch_bounds__(256) void scan_pass2(
    const __half* __restrict__ uh, const float* __restrict__ dt,
    const float* __restrict__ xdbl, const __half* __restrict__ szh,
    const float* __restrict__ A_log, const float* __restrict__ Dp,
    const float* __restrict__ hstart, __half* __restrict__ ymh)
{
    __shared__ __half Uh[2][32][64];
    __shared__ float  Dt[2][32][64];
    __shared__ __half Sz[2][32][64];
    __shared__ float  XD[2][32][32];

    const int b    = blockIdx.z;
    const int c    = blockIdx.y;
    const int d0   = blockIdx.x * 64;
    const int tid  = threadIdx.x;
    const int wid  = tid >> 5;
    const int lane = tid & 31;
    const int dq   = lane >> 2;
    const int sq   = lane & 3;
    const int dl   = wid * 8 + dq;
    const int d    = d0 + dl;

    float Ap[4], h[4];
    #pragma unroll
    for (int i = 0; i < 4; i++)
        Ap[i] = -__expf(A_log[d * DSTATE + sq * 4 + i]) * 1.4426950408889634f;
    {
        float4 h0 = *(const float4*)
            &hstart[((size_t)(b * NCHUNK + c) * DINNER + d) * DSTATE + sq * 4];
        h[0] = h0.x; h[1] = h0.y; h[2] = h0.z; h[3] = h0.w;
    }
    const float Dv = Dp[d];
    const size_t base = (size_t)b * SEQLEN * DINNER;
    const int tstart = c * CLEN;

    const int ut_t = tid >> 3, ut_g = tid & 7;
    const int xd_t = tid >> 3, xd_g = tid & 7;

    uint4  uReg, zReg;
    float4 dReg0, dReg1;
    float4 xReg;

    auto ldg_block = [&](int t0) {
        size_t go = base + (size_t)(t0 + ut_t) * DINNER + d0 + ut_g * 8;
        uReg = *(const uint4*)&uh[go];
        zReg = *(const uint4*)&szh[go];
        {
            int tt = tid >> 4, gg = tid & 15;
            dReg0 = *(const float4*)&dt[base + (size_t)(t0 + tt) * DINNER + d0 + gg * 4];
            int idx = tid + 256; tt = idx >> 4; gg = idx & 15;
            dReg1 = *(const float4*)&dt[base + (size_t)(t0 + tt) * DINNER + d0 + gg * 4];
        }
        xReg = *(const float4*)&xdbl[((size_t)b * SEQLEN + t0 + xd_t) * 32 + xd_g * 4];
    };
    auto sts_block = [&](int bf) {
        *(uint4*)&Uh[bf][ut_t][ut_g * 8] = uReg;
        *(uint4*)&Sz[bf][ut_t][ut_g * 8] = zReg;
        {
            int tt = tid >> 4, gg = tid & 15;
            *(float4*)&Dt[bf][tt][gg * 4] = dReg0;
            int idx = tid + 256; tt = idx >> 4; gg = idx & 15;
            *(float4*)&Dt[bf][tt][gg * 4] = dReg1;
        }
        *(float4*)&XD[bf][xd_t][xd_g * 4] = xReg;
    };

    ldg_block(tstart);
    sts_block(0);
    __syncthreads();

    for (int blk = 0; blk < NBLK; blk++) {
        const int bf = blk & 1;
        const bool more = (blk + 1 < NBLK);
        const int t0 = tstart + blk * 32;
        if (more) ldg_block(t0 + 32);

        #pragma unroll 4
        for (int t = 0; t < 32; t++) {
            float uv  = __half2float(Uh[bf][t][dl]);
            float dtv = Dt[bf][t][dl];
            float4 Bv = *(const float4*)&XD[bf][t][sq * 4];
            float4 Cv = *(const float4*)&XD[bf][t][16 + sq * 4];
            float du  = dtv * uv;
            float p;
            h[0] = fmaf(h[0], ex2(dtv * Ap[0]), du * Bv.x);
            h[1] = fmaf(h[1], ex2(dtv * Ap[1]), du * Bv.y);
            h[2] = fmaf(h[2], ex2(dtv * Ap[2]), du * Bv.z);
            h[3] = fmaf(h[3], ex2(dtv * Ap[3]), du * Bv.w);
            p  = h[0] * Cv.x;
            p  = fmaf(h[1], Cv.y, p);
            p  = fmaf(h[2], Cv.z, p);
            p  = fmaf(h[3], Cv.w, p);
            p += __shfl_xor_sync(0xffffffffu, p, 1);
            p += __shfl_xor_sync(0xffffffffu, p, 2);
            if (sq == 0) {
                float zv = __half2float(Sz[bf][t][dl]);
                float y  = fmaf(Dv, uv, p);
                ymh[base + (size_t)(t0 + t) * DINNER + d] = __float2half(y * zv);
            }
        }
        if (more) sts_block(bf ^ 1);
        __syncthreads();
    }
}

// ---------------- launch ---------------------------------------------------
extern "C" void kernel_launch(void* const* d_in, const int* in_sizes, int n_in,
                              void* d_out, int out_size)
{
    const float* x     = (const float*)d_in[0];
    const float* W_in  = (const float*)d_in[1];
    const float* b_in  = (const float*)d_in[2];
    const float* W_xp  = (const float*)d_in[3];
    const float* b_xp  = (const float*)d_in[4];
    const float* W_dt  = (const float*)d_in[5];
    const float* b_dt  = (const float*)d_in[6];
    const float* W_out = (const float*)d_in[7];
    const float* b_out = (const float*)d_in[8];
    const float* A_log = (const float*)d_in[9];
    const float* D_par = (const float*)d_in[10];
    float* out = (float*)d_out;

    float *dtb, *xd, *hend, *hstart, *sdt;
    __half *uh, *szh, *ymh, *xh, *w1, *w2, *w3, *wxph;
    cudaGetSymbolAddress((void**)&uh,  g_uh);
    cudaGetSymbolAddress((void**)&szh, g_szh);
    cudaGetSymbolAddress((void**)&dtb, g_dt);
    cudaGetSymbolAddress((void**)&xd,  g_xd);
    cudaGetSymbolAddress((void**)&ymh, g_ymh);
    cudaGetSymbolAddress((void**)&xh,  g_xh);
    cudaGetSymbolAddress((void**)&w1,  g_w1);
    cudaGetSymbolAddress((void**)&w2,  g_w2);
    cudaGetSymbolAddress((void**)&w3,  g_w3);
    cudaGetSymbolAddress((void**)&wxph, g_wxph);
    cudaGetSymbolAddress((void**)&hend,   g_hend);
    cudaGetSymbolAddress((void**)&hstart, g_hstart);
    cudaGetSymbolAddress((void**)&sdt,    g_sdt);

    cudaFuncSetAttribute(gemm_fp16<0>, cudaFuncAttributeMaxDynamicSharedMemorySize, GEMM_SMEM_BYTES);
    cudaFuncSetAttribute(gemm_fp16<1>, cudaFuncAttributeMaxDynamicSharedMemorySize, GEMM_SMEM_BYTES);
    cudaFuncSetAttribute(gemm_fp16<2>, cudaFuncAttributeMaxDynamicSharedMemorySize, GEMM_SMEM_BYTES);
    cudaFuncSetAttribute(gemm_fp16<3>, cudaFuncAttributeMaxDynamicSharedMemorySize, GEMM_SMEM_BYTES);

    // side stream + fork/join events (host handles only)
    cudaStream_t s2;
    cudaStreamCreateWithFlags(&s2, cudaStreamNonBlocking);
    cudaEvent_t eA, eP, eB, eX;
    cudaEventCreateWithFlags(&eA, cudaEventDisableTiming);
    cudaEventCreateWithFlags(&eP, cudaEventDisableTiming);
    cudaEventCreateWithFlags(&eB, cudaEventDisableTiming);
    cudaEventCreateWithFlags(&eX, cudaEventDisableTiming);

    dim3 blk(256);

    // 0a) prep x + W_in (needed by GEMM1) on main stream
    prep_x<<<PX_BLOCKS, 256>>>(x, W_in, xh, w1);
    cudaEventRecord(eA, 0);
    // 0b) prep W_dt/W_out/W_xp(padded half) on s2, overlapping GEMM1
    cudaStreamWaitEvent(s2, eA, 0);
    prep_w<<<PW_BLOCKS, 256, 0, s2>>>(W_dt, W_out, W_xp, w2, w3, wxph);
    cudaEventRecord(eP, s2);

    // 1) xz = x @ W_in + b_in; split+silu -> uh, szh (both half)
    gemm_fp16<0><<<dim3(4096 / 128, MM / 128), blk, GEMM_SMEM_BYTES>>>(
        xh, w1, b_in, nullptr, uh, szh, MM, 4096, DMODEL);
    cudaEventRecord(eB, 0);

    // 2) xdbl = u @ W_xproj + b_xproj on s2 (tensor-core GEMM, EPI 3),
    //    overlapping GEMM2; s2 already ordered after prep_w -> wxph ready
    cudaStreamWaitEvent(s2, eB, 0);
    gemm_fp16<3><<<dim3(1, MM / 128), blk, GEMM_SMEM_BYTES, s2>>>(
        uh, wxph, b_xp, xd, nullptr, nullptr, MM, 128, DINNER);
    cudaEventRecord(eX, s2);

    // 3) dt = softplus(u @ W_dt + b_dt) on main (needs w2 from prep_w)
    cudaStreamWaitEvent(0, eP, 0);
    gemm_fp16<1><<<dim3(DINNER / 128, MM / 128), blk, GEMM_SMEM_BYTES>>>(
        uh, w2, b_dt, dtb, nullptr, nullptr, MM, DINNER, DINNER);

    // join: scan needs xd from s2
    cudaStreamWaitEvent(0, eX, 0);

    // 4) chunked selective scan + fuse * silu(z) -> ym half
    scan_pass1<<<dim3(DINNER / 64, NCHUNK - 1, NBATCH), 256>>>(
        uh, dtb, xd, A_log, hend, sdt);
    scan_fix<<<NBATCH * DINNER * DSTATE / 256, 256>>>(A_log, hend, sdt, hstart);
    scan_pass2<<<dim3(DINNER / 64, NCHUNK, NBATCH), 256>>>(
        uh, dtb, xd, szh, A_log, D_par, hstart, ymh);

    // 5) out = ym @ W_out + b_out
    gemm_fp16<2><<<dim3(DMODEL / 128, MM / 128), blk, GEMM_SMEM_BYTES>>>(
        ymh, w3, b_out, out, nullptr, nullptr, MM, DMODEL, DINNER);
}